// round 1
// baseline (speedup 1.0000x reference)
#include <cuda_runtime.h>
#include <math.h>

// Problem constants (fixed by the reference)
#define EMB     64
#define CLUS    64
#define SEQV    5
#define ALPHA   0.2f
#define KDEC    0.1f

// Precomputed transposed column-softmax of w_raw: g_Wt[d*64 + c] = W[c][d]
__device__ float g_Wt[CLUS * CLUS];

// ---------------------------------------------------------------------------
// Kernel 1: W = softmax(w_raw * 500, axis=0), stored transposed.
// One block of 64 threads; thread d owns column d.
// ---------------------------------------------------------------------------
__global__ void prep_w_kernel(const float* __restrict__ w_raw) {
    int d = threadIdx.x;          // column index
    float col[CLUS];
    float m = -INFINITY;
#pragma unroll
    for (int c = 0; c < CLUS; c++) {
        float v = w_raw[c * CLUS + d] * 500.0f;   // 100 * GAMMA2
        col[c] = v;
        m = fmaxf(m, v);
    }
    float Z = 0.0f;
#pragma unroll
    for (int c = 0; c < CLUS; c++) {
        col[c] = __expf(col[c] - m);
        Z += col[c];
    }
    float inv = 1.0f / Z;
#pragma unroll
    for (int c = 0; c < CLUS; c++) {
        g_Wt[d * CLUS + c] = col[c] * inv;        // transposed store (contiguous)
    }
}

// ---------------------------------------------------------------------------
// Main kernel: one warp per batch element. Lane l owns vector elements
// {2l, 2l+1} of every 64-wide row -> coalesced 256B float2 gathers,
// warp-shuffle reductions only.
// ---------------------------------------------------------------------------
__global__ __launch_bounds__(256) void rumc_kernel(
    const int*   __restrict__ u,
    const int*   __restrict__ X,
    const int*   __restrict__ y,
    const float* __restrict__ item_emb,
    const float* __restrict__ user_emb,
    const float* __restrict__ ae_raw,
    float*       __restrict__ out,
    int B)
{
    __shared__ float sWt[CLUS * CLUS];   // 16 KB
    __shared__ float sAey[8][CLUS];      // 2 KB (one 64-vec per warp)

    const int tid  = threadIdx.x;
    const int warp = tid >> 5;
    const int lane = tid & 31;

    // Stage Wt into shared (whole block cooperates)
    for (int i = tid; i < CLUS * CLUS; i += 256) sWt[i] = g_Wt[i];
    __syncthreads();

    const int b = blockIdx.x * 8 + warp;
    if (b >= B) return;

    const unsigned FULL = 0xffffffffu;

    // ---- ae[y] : softmax(ae_raw[y] * 50) ----
    const int yi = y[b];
    float2 ar = *(const float2*)(ae_raw + (size_t)yi * CLUS + lane * 2);
    float a0 = ar.x * 50.0f;    // 10 * GAMMA1
    float a1 = ar.y * 50.0f;
    float m = fmaxf(a0, a1);
#pragma unroll
    for (int off = 16; off; off >>= 1)
        m = fmaxf(m, __shfl_xor_sync(FULL, m, off));
    float e0 = __expf(a0 - m);
    float e1 = __expf(a1 - m);
    float Z = e0 + e1;
#pragma unroll
    for (int off = 16; off; off >>= 1)
        Z += __shfl_xor_sync(FULL, Z, off);
    float invZ = 1.0f / Z;
    sAey[warp][2 * lane]     = e0 * invZ;
    sAey[warp][2 * lane + 1] = e1 * invZ;
    __syncwarp();

    // ---- v = W @ ae[y]  (lane owns c = 2*lane, 2*lane+1) ----
    float vx = 0.0f, vy = 0.0f;
    const float* aey = sAey[warp];
#pragma unroll
    for (int d = 0; d < CLUS; d++) {
        float a = aey[d];                                   // smem broadcast
        float2 wt = *(const float2*)(sWt + d * CLUS + 2 * lane); // conflict-free
        vx = fmaf(wt.x, a, vx);
        vy = fmaf(wt.y, a, vy);
    }

    // ---- y embedding (padding row 0 -> zero) ----
    float2 ye;
    if (yi == 0) { ye.x = 0.0f; ye.y = 0.0f; }
    else ye = *(const float2*)(item_emb + (size_t)yi * EMB + lane * 2);

    // ---- per-step scores ----
    float  sc[SEQV];
    float2 xe[SEQV];
#pragma unroll
    for (int s = 0; s < SEQV; s++) {
        const int xi = X[b * SEQV + s];

        // softmax(ae_raw[xi]*50) folded into fac = (sum e_c * v_c) / (sum e_c)
        float2 axr = *(const float2*)(ae_raw + (size_t)xi * CLUS + lane * 2);
        float b0 = axr.x * 50.0f;
        float b1 = axr.y * 50.0f;
        float mm = fmaxf(b0, b1);
#pragma unroll
        for (int off = 16; off; off >>= 1)
            mm = fmaxf(mm, __shfl_xor_sync(FULL, mm, off));
        float f0 = __expf(b0 - mm);
        float f1 = __expf(b1 - mm);
        float num = f0 * vx + f1 * vy;
        float den = f0 + f1;
#pragma unroll
        for (int off = 16; off; off >>= 1) {
            num += __shfl_xor_sync(FULL, num, off);
            den += __shfl_xor_sync(FULL, den, off);
        }
        float fac = num / den;

        // item embedding (padding row 0 -> zero)
        float2 x2;
        if (xi == 0) { x2.x = 0.0f; x2.y = 0.0f; }
        else x2 = *(const float2*)(item_emb + (size_t)xi * EMB + lane * 2);
        xe[s] = x2;

        float dot = x2.x * ye.x + x2.y * ye.y;
#pragma unroll
        for (int off = 16; off; off >>= 1)
            dot += __shfl_xor_sync(FULL, dot, off);

        const float tf = 1.0f - (float)(SEQV - 1 - s) * KDEC;  // 0.6 .. 1.0
        sc[s] = dot * __expf(fac) * tf;                        // BETA = 1
    }

    // ---- softmax over SEQ (all lanes hold identical sc[]) ----
    float ms = sc[0];
#pragma unroll
    for (int s = 1; s < SEQV; s++) ms = fmaxf(ms, sc[s]);
    float Zs = 0.0f;
#pragma unroll
    for (int s = 0; s < SEQV; s++) {
        sc[s] = __expf(sc[s] - ms);
        Zs += sc[s];
    }
    float invZs = 1.0f / Zs;

    // ---- p = sum_s z_s * X_emb_s ; p_u = alpha*p + user_emb[u] ----
    float px = 0.0f, py = 0.0f;
#pragma unroll
    for (int s = 0; s < SEQV; s++) {
        float zs = sc[s] * invZs;
        px = fmaf(xe[s].x, zs, px);
        py = fmaf(xe[s].y, zs, py);
    }
    const int ui = u[b];
    float2 ue = *(const float2*)(user_emb + (size_t)ui * EMB + lane * 2);
    float pux = fmaf(px, ALPHA, ue.x);
    float puy = fmaf(py, ALPHA, ue.y);

    float d = pux * ye.x + puy * ye.y;
#pragma unroll
    for (int off = 16; off; off >>= 1)
        d += __shfl_xor_sync(FULL, d, off);

    if (lane == 0) out[b] = 1.0f / (1.0f + __expf(-d));
}

// ---------------------------------------------------------------------------
// Launcher
// Inputs (metadata order): u[int B], X[int B*5], y[int B],
//   item_emb[f32 (I+1)*64], user_emb[f32 U*64], ae_raw[f32 (I+1)*64],
//   w_raw[f32 64*64].  Output: f32 [B].
// ---------------------------------------------------------------------------
extern "C" void kernel_launch(void* const* d_in, const int* in_sizes, int n_in,
                              void* d_out, int out_size) {
    const int*   u        = (const int*)  d_in[0];
    const int*   X        = (const int*)  d_in[1];
    const int*   y        = (const int*)  d_in[2];
    const float* item_emb = (const float*)d_in[3];
    const float* user_emb = (const float*)d_in[4];
    const float* ae_raw   = (const float*)d_in[5];
    const float* w_raw    = (const float*)d_in[6];
    float* out = (float*)d_out;

    const int B = in_sizes[0];

    prep_w_kernel<<<1, 64>>>(w_raw);

    const int warps_per_block = 8;
    const int blocks = (B + warps_per_block - 1) / warps_per_block;
    rumc_kernel<<<blocks, warps_per_block * 32>>>(
        u, X, y, item_emb, user_emb, ae_raw, out, B);
}

// round 2
// speedup vs baseline: 1.2797x; 1.2797x over previous
#include <cuda_runtime.h>
#include <math.h>

#define SEQV  5
#define ALPHA 0.2f

typedef unsigned long long ull;

// ---- packed f32x2 helpers (Blackwell) ----
__device__ __forceinline__ ull pk2(float x, float y) {
    ull r; asm("mov.b64 %0, {%1,%2};" : "=l"(r) : "f"(x), "f"(y)); return r;
}
__device__ __forceinline__ float2 unpk(ull v) {
    float2 r; asm("mov.b64 {%0,%1}, %2;" : "=f"(r.x), "=f"(r.y) : "l"(v)); return r;
}
__device__ __forceinline__ void fma2(ull &acc, ull a, ull b) {
    asm("fma.rn.f32x2 %0, %1, %2, %0;" : "+l"(acc) : "l"(a), "l"(b));
}

// ---- 8-lane (octet) reductions: xor offsets 1,2,4 stay inside the octet ----
__device__ __forceinline__ float octet_max(float v) {
    v = fmaxf(v, __shfl_xor_sync(0xffffffffu, v, 1));
    v = fmaxf(v, __shfl_xor_sync(0xffffffffu, v, 2));
    v = fmaxf(v, __shfl_xor_sync(0xffffffffu, v, 4));
    return v;
}
__device__ __forceinline__ float octet_sum(float v) {
    v += __shfl_xor_sync(0xffffffffu, v, 1);
    v += __shfl_xor_sync(0xffffffffu, v, 2);
    v += __shfl_xor_sync(0xffffffffu, v, 4);
    return v;
}

// ---------------------------------------------------------------------------
// One warp handles 4 batch elements (one per octet). Lane k of an octet owns
// vector elements {4k..4k+3, 32+4k..32+4k+3}  -> all loads are two float4s,
// coalesced per octet, bank-conflict-free in smem.
// ---------------------------------------------------------------------------
__global__ __launch_bounds__(256) void rumc_kernel(
    const int*   __restrict__ u,
    const int*   __restrict__ X,
    const int*   __restrict__ y,
    const float* __restrict__ item_emb,
    const float* __restrict__ user_emb,
    const float* __restrict__ ae_raw,
    const float* __restrict__ w_raw,
    float*       __restrict__ out,
    int B)
{
    __shared__ float  sWt[64 * 64];        // Wt[d][c] = softmax_col(w)[c][d], 16KB
    __shared__ float2 sAey[8][4][64];      // duplicated {a,a} per warp/octet, 16KB

    const int tid = threadIdx.x;

    // ---- W prep (per block): thread t<64 does column-softmax of column t ----
    if (tid < 64) {
        float col[64];
        float m = -1e30f;
#pragma unroll
        for (int c = 0; c < 64; c++) {
            float v = w_raw[c * 64 + tid] * 500.0f;   // 100 * GAMMA2
            col[c] = v;
            m = fmaxf(m, v);
        }
        float Z = 0.0f;
#pragma unroll
        for (int c = 0; c < 64; c++) { col[c] = __expf(col[c] - m); Z += col[c]; }
        float inv = 1.0f / Z;
        // staggered store to avoid 32-way bank conflicts on row writes
#pragma unroll
        for (int i = 0; i < 64; i++) {
            int c = (tid + i) & 63;
            sWt[tid * 64 + c] = col[c] * inv;         // Wt[t][c] = W[c][t]
        }
    }
    __syncthreads();

    const int warp = tid >> 5;
    const int lane = tid & 31;
    const int o    = lane >> 3;       // octet id (which b within warp)
    const int k    = lane & 7;        // lane within octet

    int b = blockIdx.x * 32 + warp * 4 + o;
    const bool valid = (b < B);
    if (!valid) b = B - 1;            // clamp: keep execution uniform

    // ---------------- ae[y] softmax -> smem (duplicated float2) -------------
    const int yi = y[b];
    const float* ayp = ae_raw + (size_t)yi * 64;
    float4 A0 = *(const float4*)(ayp + 4 * k);
    float4 A1 = *(const float4*)(ayp + 32 + 4 * k);
    float a[8] = {A0.x, A0.y, A0.z, A0.w, A1.x, A1.y, A1.z, A1.w};
    float m = -1e30f;
#pragma unroll
    for (int j = 0; j < 8; j++) { a[j] *= 50.0f; m = fmaxf(m, a[j]); }  // 10*GAMMA1
    m = octet_max(m);
    float Z = 0.0f;
#pragma unroll
    for (int j = 0; j < 8; j++) { a[j] = __expf(a[j] - m); Z += a[j]; }
    Z = octet_sum(Z);
    float invZ = 1.0f / Z;
#pragma unroll
    for (int j = 0; j < 8; j++) {
        int c = (j < 4) ? (4 * k + j) : (32 + 4 * k + (j - 4));
        float s = a[j] * invZ;
        sAey[warp][o][c] = make_float2(s, s);
    }
    __syncwarp();

    // ---------------- v = W @ ae[y]  (octets share W row reads) -------------
    ull acc[4] = {0ull, 0ull, 0ull, 0ull};
    const float4* Wt4 = (const float4*)sWt;
#pragma unroll 16
    for (int d = 0; d < 64; d++) {
        float4 w0 = Wt4[d * 16 + k];          // c = 4k..4k+3   (conflict-free)
        float4 w1 = Wt4[d * 16 + 8 + k];      // c = 32+4k..+3
        ull bb = *(const ull*)&sAey[warp][o][d];   // broadcast within octet
        fma2(acc[0], pk2(w0.x, w0.y), bb);
        fma2(acc[1], pk2(w0.z, w0.w), bb);
        fma2(acc[2], pk2(w1.x, w1.y), bb);
        fma2(acc[3], pk2(w1.z, w1.w), bb);
    }
    float v[8];
#pragma unroll
    for (int q = 0; q < 4; q++) {
        float2 t = unpk(acc[q]);
        v[2 * q] = t.x; v[2 * q + 1] = t.y;
    }

    // ---------------- y embedding (padding row 0 -> zero) -------------------
    float ye[8];
    if (yi == 0) {
#pragma unroll
        for (int j = 0; j < 8; j++) ye[j] = 0.0f;
    } else {
        const float* yp = item_emb + (size_t)yi * 64;
        float4 Y0 = *(const float4*)(yp + 4 * k);
        float4 Y1 = *(const float4*)(yp + 32 + 4 * k);
        ye[0]=Y0.x; ye[1]=Y0.y; ye[2]=Y0.z; ye[3]=Y0.w;
        ye[4]=Y1.x; ye[5]=Y1.y; ye[6]=Y1.z; ye[7]=Y1.w;
    }

    // ---------------- steps: scores + online softmax + p accumulation -------
    float mrun = -1e30f, Zrun = 0.0f;
    float pacc[8] = {0,0,0,0,0,0,0,0};
#pragma unroll
    for (int s = 0; s < SEQV; s++) {
        const int xi = X[b * SEQV + s];

        const float* axp = ae_raw + (size_t)xi * 64;
        float4 B0 = *(const float4*)(axp + 4 * k);
        float4 B1 = *(const float4*)(axp + 32 + 4 * k);
        float f[8] = {B0.x, B0.y, B0.z, B0.w, B1.x, B1.y, B1.z, B1.w};
        float mm = -1e30f;
#pragma unroll
        for (int j = 0; j < 8; j++) { f[j] *= 50.0f; mm = fmaxf(mm, f[j]); }
        mm = octet_max(mm);
        float num = 0.0f, den = 0.0f;
#pragma unroll
        for (int j = 0; j < 8; j++) {
            f[j] = __expf(f[j] - mm);
            num = fmaf(f[j], v[j], num);
            den += f[j];
        }
        num = octet_sum(num);
        den = octet_sum(den);
        float fac = num / den;

        float xe[8];
        if (xi == 0) {
#pragma unroll
            for (int j = 0; j < 8; j++) xe[j] = 0.0f;
        } else {
            const float* xp = item_emb + (size_t)xi * 64;
            float4 X0 = *(const float4*)(xp + 4 * k);
            float4 X1 = *(const float4*)(xp + 32 + 4 * k);
            xe[0]=X0.x; xe[1]=X0.y; xe[2]=X0.z; xe[3]=X0.w;
            xe[4]=X1.x; xe[5]=X1.y; xe[6]=X1.z; xe[7]=X1.w;
        }
        float dot = 0.0f;
#pragma unroll
        for (int j = 0; j < 8; j++) dot = fmaf(xe[j], ye[j], dot);
        dot = octet_sum(dot);

        const float tf = 0.6f + 0.1f * (float)s;      // time factor
        float sc = dot * __expf(fac) * tf;            // BETA = 1

        // online softmax update
        float mnew = fmaxf(mrun, sc);
        float r = __expf(mrun - mnew);                // 0 on first iter
        float e = __expf(sc - mnew);
        Zrun = fmaf(Zrun, r, e);
#pragma unroll
        for (int j = 0; j < 8; j++)
            pacc[j] = fmaf(pacc[j], r, e * xe[j]);
        mrun = mnew;
    }

    // ---------------- p_u = alpha * p + user_emb[u]; sigmoid(dot) -----------
    const float scale = ALPHA / Zrun;
    const int ui = u[b];
    const float* up = user_emb + (size_t)ui * 64;
    float4 U0 = *(const float4*)(up + 4 * k);
    float4 U1 = *(const float4*)(up + 32 + 4 * k);
    float ue[8] = {U0.x, U0.y, U0.z, U0.w, U1.x, U1.y, U1.z, U1.w};

    float d = 0.0f;
#pragma unroll
    for (int j = 0; j < 8; j++)
        d = fmaf(fmaf(pacc[j], scale, ue[j]), ye[j], d);
    d = octet_sum(d);

    if (valid && k == 0)
        out[b] = 1.0f / (1.0f + __expf(-d));
}

// ---------------------------------------------------------------------------
// Launcher — inputs (metadata order): u[int B], X[int B*5], y[int B],
//   item_emb[f32 (I+1)*64], user_emb[f32 U*64], ae_raw[f32 (I+1)*64],
//   w_raw[f32 64*64].  Output: f32 [B].
// ---------------------------------------------------------------------------
extern "C" void kernel_launch(void* const* d_in, const int* in_sizes, int n_in,
                              void* d_out, int out_size) {
    const int*   u        = (const int*)  d_in[0];
    const int*   X        = (const int*)  d_in[1];
    const int*   y        = (const int*)  d_in[2];
    const float* item_emb = (const float*)d_in[3];
    const float* user_emb = (const float*)d_in[4];
    const float* ae_raw   = (const float*)d_in[5];
    const float* w_raw    = (const float*)d_in[6];
    float* out = (float*)d_out;

    const int B = in_sizes[0];
    const int blocks = (B + 31) / 32;     // 32 batch elems per 256-thread block

    rumc_kernel<<<blocks, 256>>>(u, X, y, item_emb, user_emb, ae_raw, w_raw,
                                 out, B);
}

// round 3
// speedup vs baseline: 1.5038x; 1.1752x over previous
#include <cuda_runtime.h>
#include <math.h>

#define SEQV  5
#define ALPHA 0.2f

// ---- 16-lane (half-warp) reductions ----
__device__ __forceinline__ float hmax16(float v) {
    v = fmaxf(v, __shfl_xor_sync(0xffffffffu, v, 1));
    v = fmaxf(v, __shfl_xor_sync(0xffffffffu, v, 2));
    v = fmaxf(v, __shfl_xor_sync(0xffffffffu, v, 4));
    v = fmaxf(v, __shfl_xor_sync(0xffffffffu, v, 8));
    return v;
}
__device__ __forceinline__ float hsum16(float v) {
    v += __shfl_xor_sync(0xffffffffu, v, 1);
    v += __shfl_xor_sync(0xffffffffu, v, 2);
    v += __shfl_xor_sync(0xffffffffu, v, 4);
    v += __shfl_xor_sync(0xffffffffu, v, 8);
    return v;
}

// ---------------------------------------------------------------------------
// 256 threads = 8 warps = 16 batch elements per block (2 per warp, one per
// half-warp). Lane k (0..15) of a half owns vector elements 4k..4k+3, so every
// 64-float row is exactly one float4 per lane (fully coalesced 256B).
// W (column-softmax of w_raw, transposed) lives in smem in a float4-swizzled
// layout: logical chunk kk of row d stored at slot (kk+d)&15 -> conflict-free
// stores in prep AND conflict-free broadcast loads in the mat-vec.
// ---------------------------------------------------------------------------
__global__ __launch_bounds__(256, 5) void rumc_kernel(
    const int*   __restrict__ u,
    const int*   __restrict__ X,
    const int*   __restrict__ y,
    const float* __restrict__ item_emb,
    const float* __restrict__ user_emb,
    const float* __restrict__ ae_raw,
    const float* __restrict__ w_raw,
    float*       __restrict__ out,
    int B)
{
    __shared__ float4 sWt4[64 * 16];     // 16 KB, swizzled transposed W
    __shared__ float  sAey[16 * 68];     // 4.25 KB, ae[y] per batch elem
    __shared__ float  sRedM[4 * 64];     // 1 KB
    __shared__ float  sRedZ[4 * 64];     // 1 KB

    const int tid = threadIdx.x;

    // ================= W prep: softmax(w_raw*500, axis=0), transposed =======
    {
        const int col = tid & 63;        // column d of w_raw
        const int q   = tid >> 6;        // 0..3 : which 16-row chunk
        float w[16];
        float m = -1e30f;
#pragma unroll
        for (int i = 0; i < 16; i++) {
            float v = w_raw[(q * 16 + i) * 64 + col] * 500.0f;  // 100*GAMMA2
            w[i] = v;
            m = fmaxf(m, v);
        }
        sRedM[q * 64 + col] = m;
        __syncthreads();
        m = fmaxf(fmaxf(sRedM[col], sRedM[64 + col]),
                  fmaxf(sRedM[128 + col], sRedM[192 + col]));
        float Z = 0.0f;
#pragma unroll
        for (int i = 0; i < 16; i++) { w[i] = __expf(w[i] - m); Z += w[i]; }
        sRedZ[q * 64 + col] = Z;
        __syncthreads();
        Z = sRedZ[col] + sRedZ[64 + col] + sRedZ[128 + col] + sRedZ[192 + col];
        const float inv = 1.0f / Z;
        // thread owns rows c = q*16 .. q*16+15 of column col; as chunks
        // kk = 4q+m2, stored swizzled at slot (kk+col)&15 of row col.
#pragma unroll
        for (int m2 = 0; m2 < 4; m2++) {
            const int kk = q * 4 + m2;
            float4 val = make_float4(w[4 * m2] * inv, w[4 * m2 + 1] * inv,
                                     w[4 * m2 + 2] * inv, w[4 * m2 + 3] * inv);
            sWt4[col * 16 + ((kk + col) & 15)] = val;
        }
    }
    __syncthreads();

    // ================= per-batch-element work ================================
    const int warp = tid >> 5;
    const int lane = tid & 31;
    const int k    = lane & 15;          // lane within half
    const int bi   = warp * 2 + (lane >> 4);

    int b = blockIdx.x * 16 + bi;
    const bool valid = (b < B);
    if (!valid) b = B - 1;

    // ---- ae[y] = softmax(ae_raw[y]*50) -> smem (one copy per b) ----
    const int yi = y[b];
    float4 A = *(const float4*)(ae_raw + (size_t)yi * 64 + 4 * k);
    float a0 = A.x * 50.0f, a1 = A.y * 50.0f, a2 = A.z * 50.0f, a3 = A.w * 50.0f;
    float m = hmax16(fmaxf(fmaxf(a0, a1), fmaxf(a2, a3)));
    a0 = __expf(a0 - m); a1 = __expf(a1 - m);
    a2 = __expf(a2 - m); a3 = __expf(a3 - m);
    float Z = hsum16(a0 + a1 + a2 + a3);
    float invZ = 1.0f / Z;
    *(float4*)(sAey + bi * 68 + 4 * k) =
        make_float4(a0 * invZ, a1 * invZ, a2 * invZ, a3 * invZ);
    __syncwarp();

    // ---- v[c] = sum_d W[c][d] * aey[d], lane owns c = 4k..4k+3 ----
    float v0 = 0.f, v1 = 0.f, v2 = 0.f, v3 = 0.f;
    const float* aeyp = sAey + bi * 68;
#pragma unroll 16
    for (int d = 0; d < 64; d++) {
        float4 w4 = sWt4[d * 16 + ((k + d) & 15)];
        float  ad = aeyp[d];                       // broadcast
        v0 = fmaf(w4.x, ad, v0);
        v1 = fmaf(w4.y, ad, v1);
        v2 = fmaf(w4.z, ad, v2);
        v3 = fmaf(w4.w, ad, v3);
    }

    // ---- y embedding (padding row 0 -> zero) ----
    float4 ye = make_float4(0.f, 0.f, 0.f, 0.f);
    if (yi != 0) ye = *(const float4*)(item_emb + (size_t)yi * 64 + 4 * k);

    // ---- sequence steps: scores + online softmax + weighted sum ----
    int xs[SEQV];
#pragma unroll
    for (int s = 0; s < SEQV; s++) xs[s] = X[b * SEQV + s];

    float mrun = -1e30f, Zrun = 0.0f;
    float p0 = 0.f, p1 = 0.f, p2 = 0.f, p3 = 0.f;
#pragma unroll
    for (int s = 0; s < SEQV; s++) {
        const int xi = xs[s];

        float4 F = *(const float4*)(ae_raw + (size_t)xi * 64 + 4 * k);
        float f0 = F.x * 50.0f, f1 = F.y * 50.0f;
        float f2 = F.z * 50.0f, f3 = F.w * 50.0f;
        float mm = hmax16(fmaxf(fmaxf(f0, f1), fmaxf(f2, f3)));
        f0 = __expf(f0 - mm); f1 = __expf(f1 - mm);
        f2 = __expf(f2 - mm); f3 = __expf(f3 - mm);
        float num = fmaf(f0, v0, fmaf(f1, v1, fmaf(f2, v2, f3 * v3)));
        float den = (f0 + f1) + (f2 + f3);
        num = hsum16(num);
        den = hsum16(den);
        float fac = num / den;

        float4 xe = make_float4(0.f, 0.f, 0.f, 0.f);
        if (xi != 0) xe = *(const float4*)(item_emb + (size_t)xi * 64 + 4 * k);

        float dot = fmaf(xe.x, ye.x, fmaf(xe.y, ye.y,
                    fmaf(xe.z, ye.z, xe.w * ye.w)));
        dot = hsum16(dot);

        const float tf = 0.6f + 0.1f * (float)s;   // time factor, BETA=1
        float sc = dot * __expf(fac) * tf;

        // online softmax accumulation
        float mnew = fmaxf(mrun, sc);
        float r = __expf(mrun - mnew);
        float e = __expf(sc - mnew);
        Zrun = fmaf(Zrun, r, e);
        p0 = fmaf(p0, r, e * xe.x);
        p1 = fmaf(p1, r, e * xe.y);
        p2 = fmaf(p2, r, e * xe.z);
        p3 = fmaf(p3, r, e * xe.w);
        mrun = mnew;
    }

    // ---- p_u = alpha*p + user_emb[u]; out = sigmoid(p_u . y_emb) ----
    const float scale = ALPHA / Zrun;
    const int ui = u[b];
    float4 ue = *(const float4*)(user_emb + (size_t)ui * 64 + 4 * k);

    float d = fmaf(fmaf(p0, scale, ue.x), ye.x,
              fmaf(fmaf(p1, scale, ue.y), ye.y,
              fmaf(fmaf(p2, scale, ue.z), ye.z,
                   fmaf(p3, scale, ue.w) * ye.w)));
    d = hsum16(d);

    if (valid && k == 0)
        out[b] = 1.0f / (1.0f + __expf(-d));
}

// ---------------------------------------------------------------------------
// Launcher — inputs (metadata order): u[int B], X[int B*5], y[int B],
//   item_emb[f32 (I+1)*64], user_emb[f32 U*64], ae_raw[f32 (I+1)*64],
//   w_raw[f32 64*64].  Output: f32 [B].
// ---------------------------------------------------------------------------
extern "C" void kernel_launch(void* const* d_in, const int* in_sizes, int n_in,
                              void* d_out, int out_size) {
    const int*   u        = (const int*)  d_in[0];
    const int*   X        = (const int*)  d_in[1];
    const int*   y        = (const int*)  d_in[2];
    const float* item_emb = (const float*)d_in[3];
    const float* user_emb = (const float*)d_in[4];
    const float* ae_raw   = (const float*)d_in[5];
    const float* w_raw    = (const float*)d_in[6];
    float* out = (float*)d_out;

    const int B = in_sizes[0];
    const int blocks = (B + 15) / 16;    // 16 batch elems per 256-thread block

    rumc_kernel<<<blocks, 256>>>(u, X, y, item_emb, user_emb, ae_raw, w_raw,
                                 out, B);
}

// round 4
// speedup vs baseline: 1.9342x; 1.2862x over previous
#include <cuda_runtime.h>
#include <math.h>

#define SEQV  5
#define ALPHA 0.2f

// ---- 8-lane (octet) reductions: xor 1,2,4 stay inside the octet ----
__device__ __forceinline__ float omax8(float v) {
    v = fmaxf(v, __shfl_xor_sync(0xffffffffu, v, 1));
    v = fmaxf(v, __shfl_xor_sync(0xffffffffu, v, 2));
    v = fmaxf(v, __shfl_xor_sync(0xffffffffu, v, 4));
    return v;
}
__device__ __forceinline__ float osum8(float v) {
    v += __shfl_xor_sync(0xffffffffu, v, 1);
    v += __shfl_xor_sync(0xffffffffu, v, 2);
    v += __shfl_xor_sync(0xffffffffu, v, 4);
    return v;
}

// ---------------------------------------------------------------------------
// 256 threads = 8 warps = 32 batch elements per block (4 per warp).
// Phase 1: block computes Wt[d][c] = softmax(w_raw*500, axis=0)[c][d] into
//          smem (stride-66 padded rows -> conflict-free float2 loads).
// Phase 2: each 8-lane octet computes ae[y] softmax for its b -> smem.
// Phase 3: batched mat-vec v = Wt^T-applied per warp: each W row read ONCE
//          serves 4 batch elements (amortizes the dominant smem traffic).
// Phase 4: octet-per-b epilogue (scores, online softmax, sigmoid).
// All cross-phase deps are warp-local -> __syncwarp only (one __syncthreads
// after W prep).
// ---------------------------------------------------------------------------
__global__ __launch_bounds__(256, 4) void rumc_kernel(
    const int*   __restrict__ u,
    const int*   __restrict__ X,
    const int*   __restrict__ y,
    const float* __restrict__ item_emb,
    const float* __restrict__ user_emb,
    const float* __restrict__ ae_raw,
    const float* __restrict__ w_raw,
    float*       __restrict__ out,
    int B)
{
    __shared__ float sW[64 * 66];      // Wt rows padded to 66 floats (16.9KB)
    __shared__ float sAey[32 * 68];    // ae[y] per b, padded rows (8.7KB)
    __shared__ float sV[32 * 68];      // v per b, padded rows (8.7KB)
    __shared__ float sRedM[256];
    __shared__ float sRedZ[256];

    const int tid = threadIdx.x;

    // ================= Phase 1: W prep =======================================
    {
        const int dcol = tid & 63;     // w_raw column == Wt row
        const int q    = tid >> 6;     // 0..3: 16-row chunk of w_raw
        float w[16];
        float m = -1e30f;
#pragma unroll
        for (int i = 0; i < 16; i++) {
            float v = w_raw[(q * 16 + i) * 64 + dcol] * 500.0f;  // 100*GAMMA2
            w[i] = v;
            m = fmaxf(m, v);
        }
        sRedM[q * 64 + dcol] = m;
        __syncthreads();
        m = fmaxf(fmaxf(sRedM[dcol], sRedM[64 + dcol]),
                  fmaxf(sRedM[128 + dcol], sRedM[192 + dcol]));
        float Z = 0.0f;
#pragma unroll
        for (int i = 0; i < 16; i++) { w[i] = __expf(w[i] - m); Z += w[i]; }
        sRedZ[q * 64 + dcol] = Z;
        __syncthreads();
        Z = sRedZ[dcol] + sRedZ[64 + dcol] + sRedZ[128 + dcol] + sRedZ[192 + dcol];
        const float inv = 1.0f / Z;
#pragma unroll
        for (int i = 0; i < 16; i++)
            sW[dcol * 66 + q * 16 + i] = w[i] * inv;   // Wt[dcol][c], c=16q+i
    }
    __syncthreads();

    // ================= lane/batch mapping ====================================
    const int warp = tid >> 5;
    const int lane = tid & 31;
    const int o    = lane >> 3;        // octet id -> which b within warp
    const int k8   = lane & 7;         // lane within octet

    const int bloc = warp * 4 + o;     // 0..31 within block
    int b = blockIdx.x * 32 + bloc;
    const bool valid = (b < B);
    if (!valid) b = B - 1;

    // ================= Phase 2: ae[y] softmax -> smem ========================
    const int yi = y[b];
    {
        const float* ayp = ae_raw + (size_t)yi * 64;
        float4 A0 = *(const float4*)(ayp + 4 * k8);
        float4 A1 = *(const float4*)(ayp + 32 + 4 * k8);
        float a0 = A0.x * 50.0f, a1 = A0.y * 50.0f, a2 = A0.z * 50.0f, a3 = A0.w * 50.0f;
        float a4 = A1.x * 50.0f, a5 = A1.y * 50.0f, a6 = A1.z * 50.0f, a7 = A1.w * 50.0f;
        float m = fmaxf(fmaxf(fmaxf(a0, a1), fmaxf(a2, a3)),
                        fmaxf(fmaxf(a4, a5), fmaxf(a6, a7)));
        m = omax8(m);
        a0 = __expf(a0 - m); a1 = __expf(a1 - m); a2 = __expf(a2 - m); a3 = __expf(a3 - m);
        a4 = __expf(a4 - m); a5 = __expf(a5 - m); a6 = __expf(a6 - m); a7 = __expf(a7 - m);
        float Z = osum8(((a0 + a1) + (a2 + a3)) + ((a4 + a5) + (a6 + a7)));
        float inv = 1.0f / Z;
        *(float4*)(sAey + bloc * 68 + 4 * k8) =
            make_float4(a0 * inv, a1 * inv, a2 * inv, a3 * inv);
        *(float4*)(sAey + bloc * 68 + 32 + 4 * k8) =
            make_float4(a4 * inv, a5 * inv, a6 * inv, a7 * inv);
    }
    __syncwarp();

    // ================= Phase 3: batched mat-vec (4 b per warp) ===============
    // lane owns c = {2*lane, 2*lane+1}; each Wt row read once serves 4 b.
    {
        float acc0x = 0.f, acc0y = 0.f, acc1x = 0.f, acc1y = 0.f;
        float acc2x = 0.f, acc2y = 0.f, acc3x = 0.f, acc3y = 0.f;
        const int bB = warp * 4;
        const float* aey0 = sAey + (bB + 0) * 68;
        const float* aey1 = sAey + (bB + 1) * 68;
        const float* aey2 = sAey + (bB + 2) * 68;
        const float* aey3 = sAey + (bB + 3) * 68;
#pragma unroll
        for (int d4 = 0; d4 < 16; d4++) {
            float2 w0 = *(const float2*)(sW + (4 * d4 + 0) * 66 + 2 * lane);
            float2 w1 = *(const float2*)(sW + (4 * d4 + 1) * 66 + 2 * lane);
            float2 w2 = *(const float2*)(sW + (4 * d4 + 2) * 66 + 2 * lane);
            float2 w3 = *(const float2*)(sW + (4 * d4 + 3) * 66 + 2 * lane);

            float4 a;
            a = *(const float4*)(aey0 + 4 * d4);
            acc0x = fmaf(w0.x, a.x, fmaf(w1.x, a.y, fmaf(w2.x, a.z, fmaf(w3.x, a.w, acc0x))));
            acc0y = fmaf(w0.y, a.x, fmaf(w1.y, a.y, fmaf(w2.y, a.z, fmaf(w3.y, a.w, acc0y))));
            a = *(const float4*)(aey1 + 4 * d4);
            acc1x = fmaf(w0.x, a.x, fmaf(w1.x, a.y, fmaf(w2.x, a.z, fmaf(w3.x, a.w, acc1x))));
            acc1y = fmaf(w0.y, a.x, fmaf(w1.y, a.y, fmaf(w2.y, a.z, fmaf(w3.y, a.w, acc1y))));
            a = *(const float4*)(aey2 + 4 * d4);
            acc2x = fmaf(w0.x, a.x, fmaf(w1.x, a.y, fmaf(w2.x, a.z, fmaf(w3.x, a.w, acc2x))));
            acc2y = fmaf(w0.y, a.x, fmaf(w1.y, a.y, fmaf(w2.y, a.z, fmaf(w3.y, a.w, acc2y))));
            a = *(const float4*)(aey3 + 4 * d4);
            acc3x = fmaf(w0.x, a.x, fmaf(w1.x, a.y, fmaf(w2.x, a.z, fmaf(w3.x, a.w, acc3x))));
            acc3y = fmaf(w0.y, a.x, fmaf(w1.y, a.y, fmaf(w2.y, a.z, fmaf(w3.y, a.w, acc3y))));
        }
        *(float2*)(sV + (bB + 0) * 68 + 2 * lane) = make_float2(acc0x, acc0y);
        *(float2*)(sV + (bB + 1) * 68 + 2 * lane) = make_float2(acc1x, acc1y);
        *(float2*)(sV + (bB + 2) * 68 + 2 * lane) = make_float2(acc2x, acc2y);
        *(float2*)(sV + (bB + 3) * 68 + 2 * lane) = make_float2(acc3x, acc3y);
    }
    __syncwarp();

    // ================= Phase 4: per-b epilogue (octet) =======================
    // v for this b
    float4 V0 = *(const float4*)(sV + bloc * 68 + 4 * k8);
    float4 V1 = *(const float4*)(sV + bloc * 68 + 32 + 4 * k8);

    // y embedding (padding row 0 -> zero)
    float4 Y0 = make_float4(0.f, 0.f, 0.f, 0.f);
    float4 Y1 = make_float4(0.f, 0.f, 0.f, 0.f);
    if (yi != 0) {
        const float* yp = item_emb + (size_t)yi * 64;
        Y0 = *(const float4*)(yp + 4 * k8);
        Y1 = *(const float4*)(yp + 32 + 4 * k8);
    }

    int xs[SEQV];
#pragma unroll
    for (int s = 0; s < SEQV; s++) xs[s] = X[b * SEQV + s];

    float mrun = -1e30f, Zrun = 0.0f;
    float4 P0 = make_float4(0.f, 0.f, 0.f, 0.f);
    float4 P1 = make_float4(0.f, 0.f, 0.f, 0.f);

#pragma unroll
    for (int s = 0; s < SEQV; s++) {
        const int xi = xs[s];
        const float* axp = ae_raw + (size_t)xi * 64;
        float4 F0 = *(const float4*)(axp + 4 * k8);
        float4 F1 = *(const float4*)(axp + 32 + 4 * k8);
        float f0 = F0.x * 50.0f, f1 = F0.y * 50.0f, f2 = F0.z * 50.0f, f3 = F0.w * 50.0f;
        float f4 = F1.x * 50.0f, f5 = F1.y * 50.0f, f6 = F1.z * 50.0f, f7 = F1.w * 50.0f;
        float mm = fmaxf(fmaxf(fmaxf(f0, f1), fmaxf(f2, f3)),
                         fmaxf(fmaxf(f4, f5), fmaxf(f6, f7)));
        mm = omax8(mm);
        f0 = __expf(f0 - mm); f1 = __expf(f1 - mm);
        f2 = __expf(f2 - mm); f3 = __expf(f3 - mm);
        f4 = __expf(f4 - mm); f5 = __expf(f5 - mm);
        f6 = __expf(f6 - mm); f7 = __expf(f7 - mm);
        float num = fmaf(f0, V0.x, fmaf(f1, V0.y, fmaf(f2, V0.z, f3 * V0.w)));
        num = fmaf(f4, V1.x, fmaf(f5, V1.y, fmaf(f6, V1.z, fmaf(f7, V1.w, num))));
        float den = ((f0 + f1) + (f2 + f3)) + ((f4 + f5) + (f6 + f7));
        num = osum8(num);
        den = osum8(den);
        float fac = num / den;

        float4 X0 = make_float4(0.f, 0.f, 0.f, 0.f);
        float4 X1 = make_float4(0.f, 0.f, 0.f, 0.f);
        if (xi != 0) {
            const float* xp = item_emb + (size_t)xi * 64;
            X0 = *(const float4*)(xp + 4 * k8);
            X1 = *(const float4*)(xp + 32 + 4 * k8);
        }
        float dot = fmaf(X0.x, Y0.x, fmaf(X0.y, Y0.y, fmaf(X0.z, Y0.z, X0.w * Y0.w)));
        dot = fmaf(X1.x, Y1.x, fmaf(X1.y, Y1.y, fmaf(X1.z, Y1.z, fmaf(X1.w, Y1.w, dot))));
        dot = osum8(dot);

        const float tf = 0.6f + 0.1f * (float)s;   // time factor, BETA=1
        float sc = dot * __expf(fac) * tf;

        // online softmax accumulation
        float mnew = fmaxf(mrun, sc);
        float r = __expf(mrun - mnew);
        float e = __expf(sc - mnew);
        Zrun = fmaf(Zrun, r, e);
        P0.x = fmaf(P0.x, r, e * X0.x); P0.y = fmaf(P0.y, r, e * X0.y);
        P0.z = fmaf(P0.z, r, e * X0.z); P0.w = fmaf(P0.w, r, e * X0.w);
        P1.x = fmaf(P1.x, r, e * X1.x); P1.y = fmaf(P1.y, r, e * X1.y);
        P1.z = fmaf(P1.z, r, e * X1.z); P1.w = fmaf(P1.w, r, e * X1.w);
        mrun = mnew;
    }

    const float scale = ALPHA / Zrun;
    const int ui = u[b];
    const float* up = user_emb + (size_t)ui * 64;
    float4 U0 = *(const float4*)(up + 4 * k8);
    float4 U1 = *(const float4*)(up + 32 + 4 * k8);

    float d;
    d =          fmaf(P0.x, scale, U0.x) * Y0.x;
    d = fmaf(fmaf(P0.y, scale, U0.y), Y0.y, d);
    d = fmaf(fmaf(P0.z, scale, U0.z), Y0.z, d);
    d = fmaf(fmaf(P0.w, scale, U0.w), Y0.w, d);
    d = fmaf(fmaf(P1.x, scale, U1.x), Y1.x, d);
    d = fmaf(fmaf(P1.y, scale, U1.y), Y1.y, d);
    d = fmaf(fmaf(P1.z, scale, U1.z), Y1.z, d);
    d = fmaf(fmaf(P1.w, scale, U1.w), Y1.w, d);
    d = osum8(d);

    if (valid && k8 == 0)
        out[b] = 1.0f / (1.0f + __expf(-d));
}

// ---------------------------------------------------------------------------
// Launcher — inputs (metadata order): u[int B], X[int B*5], y[int B],
//   item_emb[f32 (I+1)*64], user_emb[f32 U*64], ae_raw[f32 (I+1)*64],
//   w_raw[f32 64*64].  Output: f32 [B].
// ---------------------------------------------------------------------------
extern "C" void kernel_launch(void* const* d_in, const int* in_sizes, int n_in,
                              void* d_out, int out_size) {
    const int*   u        = (const int*)  d_in[0];
    const int*   X        = (const int*)  d_in[1];
    const int*   y        = (const int*)  d_in[2];
    const float* item_emb = (const float*)d_in[3];
    const float* user_emb = (const float*)d_in[4];
    const float* ae_raw   = (const float*)d_in[5];
    const float* w_raw    = (const float*)d_in[6];
    float* out = (float*)d_out;

    const int B = in_sizes[0];
    const int blocks = (B + 31) / 32;   // 32 batch elems per 256-thread block

    rumc_kernel<<<blocks, 256>>>(u, X, y, item_emb, user_emb, ae_raw, w_raw,
                                 out, B);
}

// round 6
// speedup vs baseline: 2.1981x; 1.1364x over previous
#include <cuda_runtime.h>
#include <math.h>

#define SEQV  5
#define ALPHA 0.2f

// ---- 8-lane (octet) reductions: xor 1,2,4 stay inside the octet ----
__device__ __forceinline__ float omax8(float v) {
    v = fmaxf(v, __shfl_xor_sync(0xffffffffu, v, 1));
    v = fmaxf(v, __shfl_xor_sync(0xffffffffu, v, 2));
    v = fmaxf(v, __shfl_xor_sync(0xffffffffu, v, 4));
    return v;
}
__device__ __forceinline__ float osum8(float v) {
    v += __shfl_xor_sync(0xffffffffu, v, 1);
    v += __shfl_xor_sync(0xffffffffu, v, 2);
    v += __shfl_xor_sync(0xffffffffu, v, 4);
    return v;
}

// ---------------------------------------------------------------------------
// 256 threads = 8 warps = 32 batch elements per block (4 per warp, one per
// 8-lane octet). W is column-softmaxed once per block into smem; the mat-vec
// is warp-batched so every W row read serves 4 batch elements. Gathers are
// issued as early as possible to overlap DRAM latency with compute.
// ---------------------------------------------------------------------------
__global__ __launch_bounds__(256, 4) void rumc_kernel(
    const int*   __restrict__ u,
    const int*   __restrict__ X,
    const int*   __restrict__ y,
    const float* __restrict__ item_emb,
    const float* __restrict__ user_emb,
    const float* __restrict__ ae_raw,
    const float* __restrict__ w_raw,
    float*       __restrict__ out,
    int B)
{
    __shared__ float sW[64 * 66];      // Wt rows padded to 66 floats
    __shared__ float sAV[32 * 68];     // ae[y] per b, overwritten in-place by v
    __shared__ float sRedM[256];
    __shared__ float sRedZ[256];

    const int tid  = threadIdx.x;
    const int warp = tid >> 5;
    const int lane = tid & 31;
    const int o    = lane >> 3;
    const int k8   = lane & 7;

    const int bloc = warp * 4 + o;
    int b = blockIdx.x * 32 + bloc;
    const bool valid = (b < B);
    if (!valid) b = B - 1;

    // ---- issue index loads + ae[y] gather FIRST (overlaps with W prep) ----
    const int yi = y[b];
    const int ui = u[b];
    int xs[SEQV];
#pragma unroll
    for (int s = 0; s < SEQV; s++) xs[s] = X[b * SEQV + s];

    const float* ayp = ae_raw + (size_t)yi * 64;
    float4 A0 = *(const float4*)(ayp + 4 * k8);
    float4 A1 = *(const float4*)(ayp + 32 + 4 * k8);

    // ================= W prep: softmax(w_raw*500, axis=0), transposed =======
    {
        const int dcol = tid & 63;
        const int q    = tid >> 6;
        float w[16];
        float m = -1e30f;
#pragma unroll
        for (int i = 0; i < 16; i++) {
            float v = w_raw[(q * 16 + i) * 64 + dcol] * 500.0f;  // 100*GAMMA2
            w[i] = v;
            m = fmaxf(m, v);
        }
        sRedM[q * 64 + dcol] = m;
        __syncthreads();
        m = fmaxf(fmaxf(sRedM[dcol], sRedM[64 + dcol]),
                  fmaxf(sRedM[128 + dcol], sRedM[192 + dcol]));
        float Z = 0.0f;
#pragma unroll
        for (int i = 0; i < 16; i++) { w[i] = __expf(w[i] - m); Z += w[i]; }
        sRedZ[q * 64 + dcol] = Z;
        __syncthreads();
        Z = sRedZ[dcol] + sRedZ[64 + dcol] + sRedZ[128 + dcol] + sRedZ[192 + dcol];
        const float inv = __fdividef(1.0f, Z);
#pragma unroll
        for (int i = 0; i < 16; i++)
            sW[dcol * 66 + q * 16 + i] = w[i] * inv;
    }
    __syncthreads();

    // ================= ae[y] softmax -> smem =================================
    {
        float a0 = A0.x * 50.0f, a1 = A0.y * 50.0f, a2 = A0.z * 50.0f, a3 = A0.w * 50.0f;
        float a4 = A1.x * 50.0f, a5 = A1.y * 50.0f, a6 = A1.z * 50.0f, a7 = A1.w * 50.0f;
        float m = fmaxf(fmaxf(fmaxf(a0, a1), fmaxf(a2, a3)),
                        fmaxf(fmaxf(a4, a5), fmaxf(a6, a7)));
        m = omax8(m);
        a0 = __expf(a0 - m); a1 = __expf(a1 - m); a2 = __expf(a2 - m); a3 = __expf(a3 - m);
        a4 = __expf(a4 - m); a5 = __expf(a5 - m); a6 = __expf(a6 - m); a7 = __expf(a7 - m);
        float Z = osum8(((a0 + a1) + (a2 + a3)) + ((a4 + a5) + (a6 + a7)));
        float inv = __fdividef(1.0f, Z);
        *(float4*)(sAV + bloc * 68 + 4 * k8) =
            make_float4(a0 * inv, a1 * inv, a2 * inv, a3 * inv);
        *(float4*)(sAV + bloc * 68 + 32 + 4 * k8) =
            make_float4(a4 * inv, a5 * inv, a6 * inv, a7 * inv);
    }
    __syncwarp();

    // ---- prefetch y-item row and step-0 ae row (hidden under mat-vec) ----
    float4 Y0 = make_float4(0.f, 0.f, 0.f, 0.f);
    float4 Y1 = make_float4(0.f, 0.f, 0.f, 0.f);
    if (yi != 0) {
        const float* yp = item_emb + (size_t)yi * 64;
        Y0 = *(const float4*)(yp + 4 * k8);
        Y1 = *(const float4*)(yp + 32 + 4 * k8);
    }
    const int xi0 = xs[0];
    const float* ax0 = ae_raw + (size_t)xi0 * 64;
    float4 Fc0 = *(const float4*)(ax0 + 4 * k8);
    float4 Fc1 = *(const float4*)(ax0 + 32 + 4 * k8);

    // ================= batched mat-vec: 4 b per warp ==========================
    {
        float acc0x = 0.f, acc0y = 0.f, acc1x = 0.f, acc1y = 0.f;
        float acc2x = 0.f, acc2y = 0.f, acc3x = 0.f, acc3y = 0.f;
        const int bB = warp * 4;
        const float* aey0 = sAV + (bB + 0) * 68;
        const float* aey1 = sAV + (bB + 1) * 68;
        const float* aey2 = sAV + (bB + 2) * 68;
        const float* aey3 = sAV + (bB + 3) * 68;
#pragma unroll
        for (int d4 = 0; d4 < 16; d4++) {
            float2 w0 = *(const float2*)(sW + (4 * d4 + 0) * 66 + 2 * lane);
            float2 w1 = *(const float2*)(sW + (4 * d4 + 1) * 66 + 2 * lane);
            float2 w2 = *(const float2*)(sW + (4 * d4 + 2) * 66 + 2 * lane);
            float2 w3 = *(const float2*)(sW + (4 * d4 + 3) * 66 + 2 * lane);

            float4 a;
            a = *(const float4*)(aey0 + 4 * d4);
            acc0x = fmaf(w0.x, a.x, fmaf(w1.x, a.y, fmaf(w2.x, a.z, fmaf(w3.x, a.w, acc0x))));
            acc0y = fmaf(w0.y, a.x, fmaf(w1.y, a.y, fmaf(w2.y, a.z, fmaf(w3.y, a.w, acc0y))));
            a = *(const float4*)(aey1 + 4 * d4);
            acc1x = fmaf(w0.x, a.x, fmaf(w1.x, a.y, fmaf(w2.x, a.z, fmaf(w3.x, a.w, acc1x))));
            acc1y = fmaf(w0.y, a.x, fmaf(w1.y, a.y, fmaf(w2.y, a.z, fmaf(w3.y, a.w, acc1y))));
            a = *(const float4*)(aey2 + 4 * d4);
            acc2x = fmaf(w0.x, a.x, fmaf(w1.x, a.y, fmaf(w2.x, a.z, fmaf(w3.x, a.w, acc2x))));
            acc2y = fmaf(w0.y, a.x, fmaf(w1.y, a.y, fmaf(w2.y, a.z, fmaf(w3.y, a.w, acc2y))));
            a = *(const float4*)(aey3 + 4 * d4);
            acc3x = fmaf(w0.x, a.x, fmaf(w1.x, a.y, fmaf(w2.x, a.z, fmaf(w3.x, a.w, acc3x))));
            acc3y = fmaf(w0.y, a.x, fmaf(w1.y, a.y, fmaf(w2.y, a.z, fmaf(w3.y, a.w, acc3y))));
        }
        __syncwarp();   // all aey reads done before in-place v stores
        *(float2*)(sAV + (bB + 0) * 68 + 2 * lane) = make_float2(acc0x, acc0y);
        *(float2*)(sAV + (bB + 1) * 68 + 2 * lane) = make_float2(acc1x, acc1y);
        *(float2*)(sAV + (bB + 2) * 68 + 2 * lane) = make_float2(acc2x, acc2y);
        *(float2*)(sAV + (bB + 3) * 68 + 2 * lane) = make_float2(acc3x, acc3y);
    }
    __syncwarp();

    // ================= epilogue ==============================================
    float4 V0 = *(const float4*)(sAV + bloc * 68 + 4 * k8);
    float4 V1 = *(const float4*)(sAV + bloc * 68 + 32 + 4 * k8);

    // user row: issue now, consumed only after the loop
    const float* up = user_emb + (size_t)ui * 64;
    float4 U0 = *(const float4*)(up + 4 * k8);
    float4 U1 = *(const float4*)(up + 32 + 4 * k8);

    float mrun = -1e30f, Zrun = 0.0f;
    float4 P0 = make_float4(0.f, 0.f, 0.f, 0.f);
    float4 P1 = make_float4(0.f, 0.f, 0.f, 0.f);

#pragma unroll
    for (int s = 0; s < SEQV; s++) {
        const int xi = xs[s];
        // current step's ae row (step 0 prefetched above)
        float4 F0 = Fc0, F1 = Fc1;
        // item row for this step
        float4 X0 = make_float4(0.f, 0.f, 0.f, 0.f);
        float4 X1 = make_float4(0.f, 0.f, 0.f, 0.f);
        if (xi != 0) {
            const float* xp = item_emb + (size_t)xi * 64;
            X0 = *(const float4*)(xp + 4 * k8);
            X1 = *(const float4*)(xp + 32 + 4 * k8);
        }
        // prefetch next step's ae row
        if (s + 1 < SEQV) {
            const float* axn = ae_raw + (size_t)xs[s + 1] * 64;
            Fc0 = *(const float4*)(axn + 4 * k8);
            Fc1 = *(const float4*)(axn + 32 + 4 * k8);
        }

        float f0 = F0.x * 50.0f, f1 = F0.y * 50.0f, f2 = F0.z * 50.0f, f3 = F0.w * 50.0f;
        float f4 = F1.x * 50.0f, f5 = F1.y * 50.0f, f6 = F1.z * 50.0f, f7 = F1.w * 50.0f;
        float mm = fmaxf(fmaxf(fmaxf(f0, f1), fmaxf(f2, f3)),
                         fmaxf(fmaxf(f4, f5), fmaxf(f6, f7)));
        mm = omax8(mm);
        f0 = __expf(f0 - mm); f1 = __expf(f1 - mm);
        f2 = __expf(f2 - mm); f3 = __expf(f3 - mm);
        f4 = __expf(f4 - mm); f5 = __expf(f5 - mm);
        f6 = __expf(f6 - mm); f7 = __expf(f7 - mm);
        float num = fmaf(f0, V0.x, fmaf(f1, V0.y, fmaf(f2, V0.z, f3 * V0.w)));
        num = fmaf(f4, V1.x, fmaf(f5, V1.y, fmaf(f6, V1.z, fmaf(f7, V1.w, num))));
        float den = ((f0 + f1) + (f2 + f3)) + ((f4 + f5) + (f6 + f7));
        float dot = fmaf(X0.x, Y0.x, fmaf(X0.y, Y0.y, fmaf(X0.z, Y0.z, X0.w * Y0.w)));
        dot = fmaf(X1.x, Y1.x, fmaf(X1.y, Y1.y, fmaf(X1.z, Y1.z, fmaf(X1.w, Y1.w, dot))));
        num = osum8(num);
        den = osum8(den);
        dot = osum8(dot);
        float fac = __fdividef(num, den);

        const float tf = 0.6f + 0.1f * (float)s;     // time factor, BETA=1
        float sc = dot * __expf(fac) * tf;

        // online softmax accumulation
        float mnew = fmaxf(mrun, sc);
        float r = __expf(mrun - mnew);
        float e = __expf(sc - mnew);
        Zrun = fmaf(Zrun, r, e);
        P0.x = fmaf(P0.x, r, e * X0.x); P0.y = fmaf(P0.y, r, e * X0.y);
        P0.z = fmaf(P0.z, r, e * X0.z); P0.w = fmaf(P0.w, r, e * X0.w);
        P1.x = fmaf(P1.x, r, e * X1.x); P1.y = fmaf(P1.y, r, e * X1.y);
        P1.z = fmaf(P1.z, r, e * X1.z); P1.w = fmaf(P1.w, r, e * X1.w);
        mrun = mnew;
    }

    const float scale = __fdividef(ALPHA, Zrun);
    float d;
    d =          fmaf(P0.x, scale, U0.x) * Y0.x;
    d = fmaf(fmaf(P0.y, scale, U0.y), Y0.y, d);
    d = fmaf(fmaf(P0.z, scale, U0.z), Y0.z, d);
    d = fmaf(fmaf(P0.w, scale, U0.w), Y0.w, d);
    d = fmaf(fmaf(P1.x, scale, U1.x), Y1.x, d);
    d = fmaf(fmaf(P1.y, scale, U1.y), Y1.y, d);
    d = fmaf(fmaf(P1.z, scale, U1.z), Y1.z, d);
    d = fmaf(fmaf(P1.w, scale, U1.w), Y1.w, d);
    d = osum8(d);

    if (valid && k8 == 0)
        out[b] = __fdividef(1.0f, 1.0f + __expf(-d));
}

// ---------------------------------------------------------------------------
// Launcher — inputs (metadata order): u[int B], X[int B*5], y[int B],
//   item_emb[f32 (I+1)*64], user_emb[f32 U*64], ae_raw[f32 (I+1)*64],
//   w_raw[f32 64*64].  Output: f32 [B].
// ---------------------------------------------------------------------------
extern "C" void kernel_launch(void* const* d_in, const int* in_sizes, int n_in,
                              void* d_out, int out_size) {
    const int*   u        = (const int*)  d_in[0];
    const int*   X        = (const int*)  d_in[1];
    const int*   y        = (const int*)  d_in[2];
    const float* item_emb = (const float*)d_in[3];
    const float* user_emb = (const float*)d_in[4];
    const float* ae_raw   = (const float*)d_in[5];
    const float* w_raw    = (const float*)d_in[6];
    float* out = (float*)d_out;

    const int B = in_sizes[0];
    const int blocks = (B + 31) / 32;

    rumc_kernel<<<blocks, 256>>>(u, X, y, item_emb, user_emb, ae_raw, w_raw,
                                 out, B);
}